// round 3
// baseline (speedup 1.0000x reference)
#include <cuda_runtime.h>
#include <math.h>

// Problem dims
#define H  8
#define NN 8
#define D  512
#define C  64
#define C2 32
#define I  96
#define SCALE (1.0f/24.0f)   // 1/sqrt(c*kk*kk) = 1/sqrt(576)

// Output packing (T, M, P, w) concatenated, float32
#define SZ_T  (NN*C*I*I)       // 4,718,592
#define OFF_T 0
#define OFF_M (OFF_T + SZ_T)
#define SZ_M  (NN*H*C2)        // 2,048
#define OFF_P (OFF_M + SZ_M)
#define SZ_P  (NN*H*C*I*I)     // 37,748,736
#define OFF_W (OFF_P + SZ_P)

// ---------------- scratch (static device globals; no runtime alloc) ----------------
__device__ __align__(16) float g_y  [H*NN*C2];
__device__ __align__(16) float g_M  [NN*H*C2];
__device__ __align__(16) float g_Ak [NN*H*C];
__device__ __align__(16) float g_Av [NN*H*C];
__device__ __align__(16) float g_Bxk[H*C*I];
__device__ __align__(16) float g_Byk[H*C*I];
__device__ __align__(16) float g_Vx [H*C*I];
__device__ __align__(16) float g_Vy [H*C*I];
__device__ __align__(16) float g_S2 [9*C*C];
__device__ __align__(16) float g_Cs [NN*H*C*9];
__device__ __align__(16) float g_Gx [H*C*3*I];
__device__ __align__(16) float g_Gy [H*C*3*I];

// ---------------- K1: y = X @ lin_w^T + lin_b  (per (h,c2) block) ----------------
__global__ void k_y(const float* __restrict__ X, const float* __restrict__ lw,
                    const float* __restrict__ lb) {
    int b = blockIdx.x; int h = b >> 5; int c2 = b & 31;
    int tid = threadIdx.x;
    float part[NN];
#pragma unroll
    for (int n = 0; n < NN; n++) part[n] = 0.f;
    for (int d = tid; d < D; d += 256) {
        float w = lw[(h*C2 + c2)*D + d];
#pragma unroll
        for (int n = 0; n < NN; n++) part[n] += w * X[(h*NN + n)*D + d];
    }
    __shared__ float red[NN*256];
#pragma unroll
    for (int n = 0; n < NN; n++) red[n*256 + tid] = part[n];
    __syncthreads();
    for (int s = 128; s > 0; s >>= 1) {
        if (tid < s) {
#pragma unroll
            for (int n = 0; n < NN; n++) red[n*256 + tid] += red[n*256 + tid + s];
        }
        __syncthreads();
    }
    if (tid < NN)
        g_y[(h*NN + tid)*C2 + c2] = red[tid*256] + lb[h*C2 + c2];
}

// ---------------- K2: BatchNorm over n (biased var) + ReLU -> M ----------------
__global__ void k_bn(const float* __restrict__ gamma, const float* __restrict__ beta,
                     float* __restrict__ out) {
    int h = blockIdx.x;
    int t = threadIdx.x;
    int n = t >> 5, c2 = t & 31;
    float yv = g_y[(h*NN + n)*C2 + c2];
    float mu = 0.f;
#pragma unroll
    for (int k = 0; k < NN; k++) mu += g_y[(h*NN + k)*C2 + c2];
    mu *= (1.0f/NN);
    float m2 = 0.f;
#pragma unroll
    for (int k = 0; k < NN; k++) { float v = g_y[(h*NN + k)*C2 + c2] - mu; m2 += v*v; }
    float var = m2 * (1.0f/NN);
    float m = (yv - mu) * rsqrtf(var + 1e-5f) * gamma[h*C2 + c2] + beta[h*C2 + c2];
    m = fmaxf(m, 0.f);
    g_M[(n*H + h)*C2 + c2] = m;
    out[OFF_M + (n*H + h)*C2 + c2] = m;
}

// ---------------- K3: A_k / A_v  (constant parts of kp / vp) ----------------
__global__ void k_A(const float* __restrict__ kw, const float* __restrict__ kb,
                    const float* __restrict__ vw, const float* __restrict__ vb) {
    int b = blockIdx.x; int n = b >> 3; int h = b & 7;
    int d = threadIdx.x;   // 64
    const float* kwr = kw + (h*C + d)*C;
    const float* vwr = vw + (h*C + d)*C;
    const float* mr  = g_M + (n*H + h)*C2;
    float ak = 0.f, av = 0.f;
#pragma unroll
    for (int c2 = 0; c2 < C2; c2++) {
        float m = mr[c2];
        ak += (kwr[c2] + kwr[c2 + C2]) * m;
        av += (vwr[c2] + vwr[c2 + C2]) * m;
    }
    g_Ak[(n*H + h)*C + d] = ak + kb[h*C + d];
    g_Av[(n*H + h)*C + d] = av + vb[h*C + d];
}

// ---------------- K4: 1D fields Bx_k, By_k, Vx, Vy ----------------
__global__ void k_B(const float* __restrict__ kw, const float* __restrict__ vw,
                    const float* __restrict__ px, const float* __restrict__ py) {
    int b = blockIdx.x;       // h*C + cc
    int h = b >> 6; int cc = b & 63;
    int p = threadIdx.x;      // 96
    const float* kwr = kw + (h*C + cc)*C;
    const float* vwr = vw + (h*C + cc)*C;
    float bx = 0.f, by = 0.f, vx = 0.f, vy = 0.f;
#pragma unroll 8
    for (int c2 = 0; c2 < C2; c2++) {
        float pxv = px[c2*I + p];
        float pyv = py[c2*I + p];
        bx += kwr[c2]      * pxv;
        by += kwr[c2 + C2] * pyv;
        vx += vwr[c2]      * pxv;
        vy += vwr[c2 + C2] * pyv;
    }
    g_Bxk[b*I + p] = bx;
    g_Byk[b*I + p] = by;
    g_Vx [b*I + p] = vx;
    g_Vy [b*I + p] = vy;
}

// ---------------- K5: S2[vyvx][c][o] = sum over valid (ky,kx) of sw ----------------
__global__ void k_S2(const float* __restrict__ sw) {
    int o = blockIdx.x, c = threadIdx.x;
    float s[9];
    const float* p = sw + (o*C + c)*9;
#pragma unroll
    for (int k = 0; k < 9; k++) s[k] = p[k];
#pragma unroll
    for (int vy = 0; vy < 3; vy++) {
#pragma unroll
        for (int vx = 0; vx < 3; vx++) {
            float acc = 0.f;
#pragma unroll
            for (int ky = 0; ky < 3; ky++) {
                if (vy == 0 && ky == 0) continue;
                if (vy == 2 && ky == 2) continue;
#pragma unroll
                for (int kx = 0; kx < 3; kx++) {
                    if (vx == 0 && kx == 0) continue;
                    if (vx == 2 && kx == 2) continue;
                    acc += s[ky*3 + kx];
                }
            }
            g_S2[((vy*3 + vx)*C + c)*C + o] = acc;
        }
    }
}

// ---------------- K6: Cs[n,h,o,vyvx] (includes sb, pre-scaled) ----------------
__global__ void k_Cs(const float* __restrict__ sb) {
    int b = blockIdx.x;     // n*H + h
    int o = threadIdx.x;    // 64
    __shared__ float sA[C];
    sA[o] = g_Ak[b*C + o];
    __syncthreads();
    float sbv = sb[o];
#pragma unroll
    for (int v = 0; v < 9; v++) {
        float acc = 0.f;
#pragma unroll 8
        for (int c = 0; c < C; c++)
            acc += sA[c] * g_S2[(v*C + c)*C + o];
        g_Cs[(b*C + o)*9 + v] = (acc + sbv) * SCALE;
    }
}

// ---------------- K7: Gx[h,o,vy,jj] and Gy[h,o,vx,ii] (pre-scaled) ----------------
__global__ void k_G(const float* __restrict__ sw) {
    int b = blockIdx.x;
    int v   = b % 3;
    int o   = (b/3) % C;
    int h   = (b/(3*C)) % H;
    int tab = b / (3*C*H);     // 0 = Gx, 1 = Gy
    int p = threadIdx.x;       // 96
    __shared__ float cs[C*3];
    for (int t = p; t < C*3; t += 96) {
        int c = t/3, k = t%3;
        float acc = 0.f;
#pragma unroll
        for (int q = 0; q < 3; q++) {
            if (v == 0 && q == 0) continue;
            if (v == 2 && q == 2) continue;
            acc += (tab == 0) ? sw[(o*C + c)*9 + q*3 + k]    // sum over ky (restricted by vy), k = kx
                              : sw[(o*C + c)*9 + k*3 + q];   // sum over kx (restricted by vx), k = ky
        }
        cs[t] = acc;
    }
    __syncthreads();
    const float* src = (tab == 0) ? (g_Bxk + h*C*I) : (g_Byk + h*C*I);
    float val = 0.f;
#pragma unroll
    for (int k = 0; k < 3; k++) {
        int q = p + k - 1;
        if (q < 0 || q >= I) continue;
        for (int c = 0; c < C; c++)
            val += cs[c*3 + k] * src[c*I + q];
    }
    float* dst = (tab == 0) ? g_Gx : g_Gy;
    dst[((h*C + o)*3 + v)*I + p] = val * SCALE;
}

// ---------------- K8: main fused kernel — softmax + T + write P, w ----------------
__global__ void __launch_bounds__(96) k_main(const float* __restrict__ px,
                                             const float* __restrict__ py,
                                             float* __restrict__ out) {
    int t   = threadIdx.x;
    int jj4 = t % 24;
    int il  = t / 24;
    int ii  = blockIdx.x * 4 + il;
    int c   = blockIdx.y;
    int n   = blockIdx.z;
    int jj0 = jj4 * 4;
    int vy  = (ii == 0) ? 0 : (ii == (I-1) ? 2 : 1);

    float s[H][4];
    float mx0 = -1e30f, mx1 = -1e30f, mx2 = -1e30f, mx3 = -1e30f;
#pragma unroll
    for (int h = 0; h < H; h++) {
        const float4 gx = *(const float4*)(g_Gx + ((h*C + c)*3 + vy)*I + jj0);
        const float* gyr = g_Gy + (h*C + c)*3*I;
        const float* csr = g_Cs + ((n*H + h)*C + c)*9 + vy*3;
        float base = csr[1] + gyr[I + ii];       // interior vx = 1
        float s0 = base + gx.x, s1 = base + gx.y, s2 = base + gx.z, s3 = base + gx.w;
        if (jj0 == 0)       s0 = csr[0] + gyr[ii]        + gx.x;  // jj = 0  -> vx = 0
        if (jj0 == I - 4)   s3 = csr[2] + gyr[2*I + ii]  + gx.w;  // jj = 95 -> vx = 2
        s[h][0] = s0; s[h][1] = s1; s[h][2] = s2; s[h][3] = s3;
        mx0 = fmaxf(mx0, s0); mx1 = fmaxf(mx1, s1);
        mx2 = fmaxf(mx2, s2); mx3 = fmaxf(mx3, s3);
    }
    float sum0 = 0.f, sum1 = 0.f, sum2 = 0.f, sum3 = 0.f;
#pragma unroll
    for (int h = 0; h < H; h++) {
        s[h][0] = __expf(s[h][0] - mx0); sum0 += s[h][0];
        s[h][1] = __expf(s[h][1] - mx1); sum1 += s[h][1];
        s[h][2] = __expf(s[h][2] - mx2); sum2 += s[h][2];
        s[h][3] = __expf(s[h][3] - mx3); sum3 += s[h][3];
    }
    float i0 = __fdividef(1.f, sum0), i1 = __fdividef(1.f, sum1);
    float i2 = __fdividef(1.f, sum2), i3 = __fdividef(1.f, sum3);

    float4 acc = make_float4(0.f, 0.f, 0.f, 0.f);
    int pixbase = ii*I + jj0;
#pragma unroll
    for (int h = 0; h < H; h++) {
        float w0 = s[h][0]*i0, w1 = s[h][1]*i1, w2 = s[h][2]*i2, w3 = s[h][3]*i3;
        int idx = ((n*H + h)*C + c)*I*I + pixbase;
        *(float4*)(out + OFF_W + idx) = make_float4(w0, w1, w2, w3);

        float vbase = g_Av[(n*H + h)*C + c] + g_Vy[(h*C + c)*I + ii];
        const float4 vx4 = *(const float4*)(g_Vx + (h*C + c)*I + jj0);
        acc.x += w0*(vbase + vx4.x);
        acc.y += w1*(vbase + vx4.y);
        acc.z += w2*(vbase + vx4.z);
        acc.w += w3*(vbase + vx4.w);

        float4 pv;
        if (c < C2) {
            float m = g_M[(n*H + h)*C2 + c];
            const float4 p4 = *(const float4*)(px + c*I + jj0);
            pv = make_float4(m + p4.x, m + p4.y, m + p4.z, m + p4.w);
        } else {
            float vv = g_M[(n*H + h)*C2 + (c - C2)] + py[(c - C2)*I + ii];
            pv = make_float4(vv, vv, vv, vv);
        }
        *(float4*)(out + OFF_P + idx) = pv;
    }
    *(float4*)(out + OFF_T + (n*C + c)*I*I + pixbase) = acc;
}

// ---------------- launch ----------------
extern "C" void kernel_launch(void* const* d_in, const int* in_sizes, int n_in,
                              void* d_out, int out_size) {
    (void)in_sizes; (void)n_in; (void)out_size;
    const float* X     = (const float*)d_in[0];
    const float* lin_w = (const float*)d_in[1];
    const float* lin_b = (const float*)d_in[2];
    const float* gamma = (const float*)d_in[3];
    const float* beta  = (const float*)d_in[4];
    const float* px    = (const float*)d_in[5];
    const float* py    = (const float*)d_in[6];
    const float* kw    = (const float*)d_in[7];
    const float* kb    = (const float*)d_in[8];
    const float* vw    = (const float*)d_in[9];
    const float* vb    = (const float*)d_in[10];
    const float* sw    = (const float*)d_in[11];
    const float* sb    = (const float*)d_in[12];
    float* out = (float*)d_out;

    k_y  <<<H*C2, 256>>>(X, lin_w, lin_b);
    k_bn <<<H, NN*C2>>>(gamma, beta, out);
    k_A  <<<NN*H, C>>>(kw, kb, vw, vb);
    k_B  <<<H*C, I>>>(kw, vw, px, py);
    k_S2 <<<C, C>>>(sw);
    k_Cs <<<NN*H, C>>>(sb);
    k_G  <<<2*H*C*3, I>>>(sw);
    k_main<<<dim3(I/4, C, NN), 96>>>(px, py, out);
}

// round 4
// speedup vs baseline: 1.2626x; 1.2626x over previous
#include <cuda_runtime.h>
#include <math.h>

// Problem dims
#define H  8
#define NN 8
#define D  512
#define C  64
#define C2 32
#define I  96
#define SCALE (1.0f/24.0f)   // 1/sqrt(c*kk*kk) = 1/sqrt(576)

// Output packing (T, M, P, w) concatenated, float32
#define SZ_T  (NN*C*I*I)
#define OFF_T 0
#define OFF_M (OFF_T + SZ_T)
#define SZ_M  (NN*H*C2)
#define OFF_P (OFF_M + SZ_M)
#define SZ_P  (NN*H*C*I*I)
#define OFF_W (OFF_P + SZ_P)

// ---------------- scratch ----------------
__device__ __align__(16) float g_M  [NN*H*C2];
__device__ __align__(16) float g_Av [NN*H*C];
__device__ __align__(16) float g_Bxk[H*C*I];
__device__ __align__(16) float g_Byk[H*C*I];
__device__ __align__(16) float g_Vx [H*C*I];
__device__ __align__(16) float g_Vy [H*C*I];
__device__ __align__(16) float g_S2 [9*C*C];
__device__ __align__(16) float g_Cs [NN*H*C*9];
__device__ __align__(16) float g_Gx [H*C*3*I];
__device__ __align__(16) float g_Gy [H*C*3*I];

// ============================================================================
// Launch 1 (256 threads/block):
//   blocks [0,256)    : y = X@lw^T + lb, BatchNorm over n, ReLU -> g_M, out.M
//   blocks [256,768)  : 1D fields Bx_k, By_k, Vx, Vy
//   blocks [768,832)  : S2 border-sum tables
// ============================================================================
__global__ void __launch_bounds__(256) k_setup1(
    const float* __restrict__ X,  const float* __restrict__ lw,
    const float* __restrict__ lb, const float* __restrict__ gamma,
    const float* __restrict__ beta,
    const float* __restrict__ px, const float* __restrict__ py,
    const float* __restrict__ kw, const float* __restrict__ vw,
    const float* __restrict__ sw, float* __restrict__ out)
{
    int b = blockIdx.x;
    int t = threadIdx.x;

    if (b < 256) {
        // ---- y + BN + ReLU ----
        __shared__ float red[64];
        __shared__ float sy[NN];
        int h = b >> 5, c2 = b & 31;
        int wid = t >> 5, lane = t & 31;
        float part[NN];
#pragma unroll
        for (int n = 0; n < NN; n++) part[n] = 0.f;
#pragma unroll
        for (int it = 0; it < 2; it++) {
            int d = t + it*256;
            float w = lw[(h*C2 + c2)*D + d];
#pragma unroll
            for (int n = 0; n < NN; n++) part[n] += w * X[(h*NN + n)*D + d];
        }
#pragma unroll
        for (int off = 16; off; off >>= 1) {
#pragma unroll
            for (int n = 0; n < NN; n++)
                part[n] += __shfl_down_sync(0xffffffffu, part[n], off);
        }
        if (lane == 0) {
#pragma unroll
            for (int n = 0; n < NN; n++) red[wid*NN + n] = part[n];
        }
        __syncthreads();
        if (t < NN) {
            float y = lb[h*C2 + c2];
#pragma unroll
            for (int w = 0; w < 8; w++) y += red[w*NN + t];
            sy[t] = y;
        }
        __syncthreads();
        if (t < NN) {
            float mu = 0.f;
#pragma unroll
            for (int k = 0; k < NN; k++) mu += sy[k];
            mu *= (1.0f/NN);
            float m2 = 0.f;
#pragma unroll
            for (int k = 0; k < NN; k++) { float v = sy[k] - mu; m2 += v*v; }
            float var = m2 * (1.0f/NN);
            float m = (sy[t] - mu) * rsqrtf(var + 1e-5f) * gamma[h*C2 + c2] + beta[h*C2 + c2];
            m = fmaxf(m, 0.f);
            g_M[(t*H + h)*C2 + c2] = m;
            out[OFF_M + (t*H + h)*C2 + c2] = m;
        }
    } else if (b < 768) {
        // ---- 1D fields ----
        if (t >= I) return;
        int bb = b - 256;            // h*C + cc
        int h = bb >> 6, cc = bb & 63;
        int p = t;
        const float* kwr = kw + (h*C + cc)*C;
        const float* vwr = vw + (h*C + cc)*C;
        float bx = 0.f, by = 0.f, vx = 0.f, vy = 0.f;
#pragma unroll 8
        for (int c2 = 0; c2 < C2; c2++) {
            float pxv = px[c2*I + p];
            float pyv = py[c2*I + p];
            bx += kwr[c2]      * pxv;
            by += kwr[c2 + C2] * pyv;
            vx += vwr[c2]      * pxv;
            vy += vwr[c2 + C2] * pyv;
        }
        g_Bxk[bb*I + p] = bx;
        g_Byk[bb*I + p] = by;
        g_Vx [bb*I + p] = vx;
        g_Vy [bb*I + p] = vy;
    } else {
        // ---- S2 tables ----
        if (t >= C) return;
        int o = b - 768, c = t;
        float s[9];
        const float* p = sw + (o*C + c)*9;
#pragma unroll
        for (int k = 0; k < 9; k++) s[k] = p[k];
#pragma unroll
        for (int vy = 0; vy < 3; vy++) {
#pragma unroll
            for (int vx = 0; vx < 3; vx++) {
                float acc = 0.f;
#pragma unroll
                for (int ky = 0; ky < 3; ky++) {
                    if (vy == 0 && ky == 0) continue;
                    if (vy == 2 && ky == 2) continue;
#pragma unroll
                    for (int kx = 0; kx < 3; kx++) {
                        if (vx == 0 && kx == 0) continue;
                        if (vx == 2 && kx == 2) continue;
                        acc += s[ky*3 + kx];
                    }
                }
                g_S2[((vy*3 + vx)*C + c)*C + o] = acc;
            }
        }
    }
}

// ============================================================================
// Launch 2 (96 threads/block):
//   blocks [0,64)        : A_k/A_v + Cs (fused through smem)
//   blocks [64,3136)     : Gx / Gy 1D conv tables
//   blocks [3136,3648)   : P writer (pure broadcast stores)
// ============================================================================
__global__ void __launch_bounds__(96) k_setup2(
    const float* __restrict__ kw, const float* __restrict__ kb,
    const float* __restrict__ vw, const float* __restrict__ vb,
    const float* __restrict__ sw, const float* __restrict__ sb,
    const float* __restrict__ px, const float* __restrict__ py,
    float* __restrict__ out)
{
    int b = blockIdx.x;
    int t = threadIdx.x;

    if (b < 64) {
        // ---- A + Cs ----
        __shared__ float sAk[C];
        int n = b >> 3, h = b & 7;
        if (t < C) {
            int d = t;
            const float* kwr = kw + (h*C + d)*C;
            const float* vwr = vw + (h*C + d)*C;
            const float* mr  = g_M + (n*H + h)*C2;
            float ak = 0.f, av = 0.f;
#pragma unroll
            for (int c2 = 0; c2 < C2; c2++) {
                float m = mr[c2];
                ak += (kwr[c2] + kwr[c2 + C2]) * m;
                av += (vwr[c2] + vwr[c2 + C2]) * m;
            }
            g_Av[(n*H + h)*C + d] = av + vb[h*C + d];
            sAk[d] = ak + kb[h*C + d];
        }
        __syncthreads();
        if (t < C) {
            int o = t;
            float sbv = sb[o];
#pragma unroll
            for (int v = 0; v < 9; v++) {
                float acc = 0.f;
#pragma unroll 8
                for (int c = 0; c < C; c++)
                    acc += sAk[c] * g_S2[(v*C + c)*C + o];
                g_Cs[((n*H + h)*C + o)*9 + v] = (acc + sbv) * SCALE;
            }
        }
    } else if (b < 64 + 3072) {
        // ---- Gx / Gy ----
        int b2 = b - 64;
        int v   = b2 % 3;
        int o   = (b2/3) % C;
        int h   = (b2/(3*C)) % H;
        int tab = b2 / (3*C*H);
        int p = t;
        __shared__ float cs[C*3];
        for (int q = p; q < C*3; q += 96) {
            int c = q/3, k = q%3;
            float acc = 0.f;
#pragma unroll
            for (int qq = 0; qq < 3; qq++) {
                if (v == 0 && qq == 0) continue;
                if (v == 2 && qq == 2) continue;
                acc += (tab == 0) ? sw[(o*C + c)*9 + qq*3 + k]
                                  : sw[(o*C + c)*9 + k*3 + qq];
            }
            cs[q] = acc;
        }
        __syncthreads();
        const float* src = (tab == 0) ? (g_Bxk + h*C*I) : (g_Byk + h*C*I);
        float val = 0.f;
#pragma unroll
        for (int k = 0; k < 3; k++) {
            int q = p + k - 1;
            if (q < 0 || q >= I) continue;
            for (int c = 0; c < C; c++)
                val += cs[c*3 + k] * src[c*I + q];
        }
        float* dst = (tab == 0) ? g_Gx : g_Gy;
        dst[((h*C + o)*3 + v)*I + p] = val * SCALE;
    } else {
        // ---- P writer ----
        int b2 = b - 3136;                  // 512 blocks: (n, c)
        int c = b2 & 63, n = b2 >> 6;
        int j4 = t % 24, hh = t / 24;       // hh in [0,4); handles h = hh, hh+4
        int jj0 = j4 * 4;
        if (c < C2) {
            const float4 p4 = *(const float4*)(px + c*I + jj0);
#pragma unroll
            for (int g = 0; g < 2; g++) {
                int h = hh + g*4;
                float m = g_M[(n*H + h)*C2 + c];
                float4 pv = make_float4(m + p4.x, m + p4.y, m + p4.z, m + p4.w);
                float* dst = out + OFF_P + (size_t)((n*H + h)*C + c)*I*I + jj0;
#pragma unroll 4
                for (int ii = 0; ii < I; ii++)
                    *(float4*)(dst + ii*I) = pv;
            }
        } else {
            int c2 = c - C2;
            float m0 = g_M[(n*H + hh)*C2 + c2];
            float m1 = g_M[(n*H + hh + 4)*C2 + c2];
            float* d0 = out + OFF_P + (size_t)((n*H + hh)*C + c)*I*I + jj0;
            float* d1 = out + OFF_P + (size_t)((n*H + hh + 4)*C + c)*I*I + jj0;
#pragma unroll 4
            for (int ii = 0; ii < I; ii++) {
                float pyv = __ldg(py + c2*I + ii);
                float v0 = m0 + pyv, v1 = m1 + pyv;
                *(float4*)(d0 + ii*I) = make_float4(v0, v0, v0, v0);
                *(float4*)(d1 + ii*I) = make_float4(v1, v1, v1, v1);
            }
        }
    }
}

// ============================================================================
// Launch 3: softmax over heads + w write + T accumulate
// grid (24, 64, 8), 96 threads
// ============================================================================
__global__ void __launch_bounds__(96) k_WT(float* __restrict__ out) {
    __shared__ float sGx[H][I];    // vy = 1 slice
    __shared__ float sVx[H][I];
    __shared__ float sBase[32], sE0[32], sE2[32], sVb[32];

    int t = threadIdx.x;
    int bx = blockIdx.x, c = blockIdx.y, n = blockIdx.z;

    if (t < 32) {
        int h = t >> 2, il = t & 3;
        int ii = bx*4 + il;
        int vy = (ii == 0) ? 0 : (ii == (I-1) ? 2 : 1);
        const float* cs = g_Cs + ((n*H + h)*C + c)*9 + vy*3;
        const float* gy = g_Gy + (h*C + c)*3*I;
        sBase[t] = cs[1] + gy[I + ii];
        sE0[t]   = cs[0] + gy[ii];
        sE2[t]   = cs[2] + gy[2*I + ii];
        sVb[t]   = g_Av[(n*H + h)*C + c] + g_Vy[(h*C + c)*I + ii];
    }
#pragma unroll
    for (int q = t; q < 2*I; q += 96) {     // 192 float4 slots = 8h x 24
        int h = q / 24, j4 = q % 24;
        *(float4*)&sGx[h][j4*4] = *(const float4*)(g_Gx + ((h*C + c)*3 + 1)*I + j4*4);
        *(float4*)&sVx[h][j4*4] = *(const float4*)(g_Vx + (h*C + c)*I + j4*4);
    }
    __syncthreads();

    int j4 = t % 24, il = t / 24;
    int ii = bx*4 + il, jj0 = j4*4;
    int vy = (ii == 0) ? 0 : (ii == (I-1) ? 2 : 1);
    int hb = il;                            // h*4+il base index into staged tables

    float s[H][4];
    float mx0 = -1e30f, mx1 = -1e30f, mx2 = -1e30f, mx3 = -1e30f;
#pragma unroll
    for (int h = 0; h < H; h++) {
        float4 gx = (vy == 1) ? *(const float4*)&sGx[h][jj0]
                              : *(const float4*)(g_Gx + ((h*C + c)*3 + vy)*I + jj0);
        float base = sBase[h*4 + hb];
        float s0 = base + gx.x, s1 = base + gx.y, s2 = base + gx.z, s3 = base + gx.w;
        if (jj0 == 0)     s0 = sE0[h*4 + hb] + gx.x;
        if (jj0 == I - 4) s3 = sE2[h*4 + hb] + gx.w;
        s[h][0] = s0; s[h][1] = s1; s[h][2] = s2; s[h][3] = s3;
        mx0 = fmaxf(mx0, s0); mx1 = fmaxf(mx1, s1);
        mx2 = fmaxf(mx2, s2); mx3 = fmaxf(mx3, s3);
    }
    float sum0 = 0.f, sum1 = 0.f, sum2 = 0.f, sum3 = 0.f;
#pragma unroll
    for (int h = 0; h < H; h++) {
        s[h][0] = __expf(s[h][0] - mx0); sum0 += s[h][0];
        s[h][1] = __expf(s[h][1] - mx1); sum1 += s[h][1];
        s[h][2] = __expf(s[h][2] - mx2); sum2 += s[h][2];
        s[h][3] = __expf(s[h][3] - mx3); sum3 += s[h][3];
    }
    float i0 = __fdividef(1.f, sum0), i1 = __fdividef(1.f, sum1);
    float i2 = __fdividef(1.f, sum2), i3 = __fdividef(1.f, sum3);

    float4 acc = make_float4(0.f, 0.f, 0.f, 0.f);
    int pixbase = ii*I + jj0;
#pragma unroll
    for (int h = 0; h < H; h++) {
        float w0 = s[h][0]*i0, w1 = s[h][1]*i1, w2 = s[h][2]*i2, w3 = s[h][3]*i3;
        size_t idx = (size_t)((n*H + h)*C + c)*I*I + pixbase;
        *(float4*)(out + OFF_W + idx) = make_float4(w0, w1, w2, w3);

        float vb = sVb[h*4 + hb];
        const float4 vx4 = *(const float4*)&sVx[h][jj0];
        acc.x += w0*(vb + vx4.x);
        acc.y += w1*(vb + vx4.y);
        acc.z += w2*(vb + vx4.z);
        acc.w += w3*(vb + vx4.w);
    }
    *(float4*)(out + OFF_T + (size_t)(n*C + c)*I*I + pixbase) = acc;
}

// ---------------- launch ----------------
extern "C" void kernel_launch(void* const* d_in, const int* in_sizes, int n_in,
                              void* d_out, int out_size) {
    (void)in_sizes; (void)n_in; (void)out_size;
    const float* X     = (const float*)d_in[0];
    const float* lin_w = (const float*)d_in[1];
    const float* lin_b = (const float*)d_in[2];
    const float* gamma = (const float*)d_in[3];
    const float* beta  = (const float*)d_in[4];
    const float* px    = (const float*)d_in[5];
    const float* py    = (const float*)d_in[6];
    const float* kw    = (const float*)d_in[7];
    const float* kb    = (const float*)d_in[8];
    const float* vw    = (const float*)d_in[9];
    const float* vb    = (const float*)d_in[10];
    const float* sw    = (const float*)d_in[11];
    const float* sb    = (const float*)d_in[12];
    float* out = (float*)d_out;

    k_setup1<<<832, 256>>>(X, lin_w, lin_b, gamma, beta, px, py, kw, vw, sw, out);
    k_setup2<<<3648, 96>>>(kw, kb, vw, vb, sw, sb, px, py, out);
    k_WT<<<dim3(I/4, C, NN), 96>>>(out);
}

// round 5
// speedup vs baseline: 1.4358x; 1.1372x over previous
#include <cuda_runtime.h>
#include <math.h>

// Problem dims
#define H  8
#define NN 8
#define D  512
#define C  64
#define C2 32
#define I  96
#define SCALE (1.0f/24.0f)   // 1/sqrt(c*kk*kk) = 1/sqrt(576)

// Output packing (T, M, P, w) concatenated, float32
#define SZ_T  (NN*C*I*I)
#define OFF_T 0
#define OFF_M (OFF_T + SZ_T)
#define SZ_M  (NN*H*C2)
#define OFF_P (OFF_M + SZ_M)
#define SZ_P  (NN*H*C*I*I)
#define OFF_W (OFF_P + SZ_P)

// ---------------- scratch ----------------
__device__ __align__(16) float g_M  [NN*H*C2];
__device__ __align__(16) float g_Av [NN*H*C];
__device__ __align__(16) float g_Bxk[H*C*I];
__device__ __align__(16) float g_Byk[H*C*I];
__device__ __align__(16) float g_Vx [H*C*I];
__device__ __align__(16) float g_Vy [H*C*I];
__device__ __align__(16) float g_S2 [9*C*C];
__device__ __align__(16) float g_Cs [NN*H*C*9];
__device__ __align__(16) float g_Gx [H*C*3*I];
__device__ __align__(16) float g_Gy [H*C*3*I];

// ============================================================================
// Launch 1 (256 threads/block):
//   blocks [0,256)    : y = X@lw^T + lb, BatchNorm over n, ReLU -> g_M, out.M
//   blocks [256,768)  : 1D fields Bx_k, By_k, Vx, Vy
//   blocks [768,832)  : S2 border-sum tables
// ============================================================================
__global__ void __launch_bounds__(256) k_setup1(
    const float* __restrict__ X,  const float* __restrict__ lw,
    const float* __restrict__ lb, const float* __restrict__ gamma,
    const float* __restrict__ beta,
    const float* __restrict__ px, const float* __restrict__ py,
    const float* __restrict__ kw, const float* __restrict__ vw,
    const float* __restrict__ sw, float* __restrict__ out)
{
    int b = blockIdx.x;
    int t = threadIdx.x;

    if (b < 256) {
        // ---- y + BN + ReLU ----
        __shared__ float red[64];
        __shared__ float sy[NN];
        int h = b >> 5, c2 = b & 31;
        int wid = t >> 5, lane = t & 31;
        float part[NN];
#pragma unroll
        for (int n = 0; n < NN; n++) part[n] = 0.f;
#pragma unroll
        for (int it = 0; it < 2; it++) {
            int d = t + it*256;
            float w = lw[(h*C2 + c2)*D + d];
#pragma unroll
            for (int n = 0; n < NN; n++) part[n] += w * X[(h*NN + n)*D + d];
        }
#pragma unroll
        for (int off = 16; off; off >>= 1) {
#pragma unroll
            for (int n = 0; n < NN; n++)
                part[n] += __shfl_down_sync(0xffffffffu, part[n], off);
        }
        if (lane == 0) {
#pragma unroll
            for (int n = 0; n < NN; n++) red[wid*NN + n] = part[n];
        }
        __syncthreads();
        if (t < NN) {
            float y = lb[h*C2 + c2];
#pragma unroll
            for (int w = 0; w < 8; w++) y += red[w*NN + t];
            sy[t] = y;
        }
        __syncthreads();
        if (t < NN) {
            float mu = 0.f;
#pragma unroll
            for (int k = 0; k < NN; k++) mu += sy[k];
            mu *= (1.0f/NN);
            float m2 = 0.f;
#pragma unroll
            for (int k = 0; k < NN; k++) { float v = sy[k] - mu; m2 += v*v; }
            float var = m2 * (1.0f/NN);
            float m = (sy[t] - mu) * rsqrtf(var + 1e-5f) * gamma[h*C2 + c2] + beta[h*C2 + c2];
            m = fmaxf(m, 0.f);
            g_M[(t*H + h)*C2 + c2] = m;
            out[OFF_M + (t*H + h)*C2 + c2] = m;
        }
    } else if (b < 768) {
        // ---- 1D fields ----
        if (t >= I) return;
        int bb = b - 256;            // h*C + cc
        int h = bb >> 6, cc = bb & 63;
        int p = t;
        const float* kwr = kw + (h*C + cc)*C;
        const float* vwr = vw + (h*C + cc)*C;
        float bx = 0.f, by = 0.f, vx = 0.f, vy = 0.f;
#pragma unroll 8
        for (int c2 = 0; c2 < C2; c2++) {
            float pxv = px[c2*I + p];
            float pyv = py[c2*I + p];
            bx += kwr[c2]      * pxv;
            by += kwr[c2 + C2] * pyv;
            vx += vwr[c2]      * pxv;
            vy += vwr[c2 + C2] * pyv;
        }
        g_Bxk[bb*I + p] = bx;
        g_Byk[bb*I + p] = by;
        g_Vx [bb*I + p] = vx;
        g_Vy [bb*I + p] = vy;
    } else {
        // ---- S2 tables ----
        if (t >= C) return;
        int o = b - 768, c = t;
        float s[9];
        const float* p = sw + (o*C + c)*9;
#pragma unroll
        for (int k = 0; k < 9; k++) s[k] = p[k];
#pragma unroll
        for (int vy = 0; vy < 3; vy++) {
#pragma unroll
            for (int vx = 0; vx < 3; vx++) {
                float acc = 0.f;
#pragma unroll
                for (int ky = 0; ky < 3; ky++) {
                    if (vy == 0 && ky == 0) continue;
                    if (vy == 2 && ky == 2) continue;
#pragma unroll
                    for (int kx = 0; kx < 3; kx++) {
                        if (vx == 0 && kx == 0) continue;
                        if (vx == 2 && kx == 2) continue;
                        acc += s[ky*3 + kx];
                    }
                }
                g_S2[((vy*3 + vx)*C + c)*C + o] = acc;
            }
        }
    }
}

// ============================================================================
// Launch 2 (96 threads/block):
//   blocks [0,64)        : A_k/A_v + Cs (fused through smem)
//   blocks [64,3136)     : Gx / Gy 1D conv tables
// ============================================================================
__global__ void __launch_bounds__(96) k_setup2(
    const float* __restrict__ kw, const float* __restrict__ kb,
    const float* __restrict__ vw, const float* __restrict__ vb,
    const float* __restrict__ sw, const float* __restrict__ sb)
{
    int b = blockIdx.x;
    int t = threadIdx.x;

    if (b < 64) {
        // ---- A + Cs ----
        __shared__ float sAk[C];
        int n = b >> 3, h = b & 7;
        if (t < C) {
            int d = t;
            const float* kwr = kw + (h*C + d)*C;
            const float* vwr = vw + (h*C + d)*C;
            const float* mr  = g_M + (n*H + h)*C2;
            float ak = 0.f, av = 0.f;
#pragma unroll
            for (int c2 = 0; c2 < C2; c2++) {
                float m = mr[c2];
                ak += (kwr[c2] + kwr[c2 + C2]) * m;
                av += (vwr[c2] + vwr[c2 + C2]) * m;
            }
            g_Av[(n*H + h)*C + d] = av + vb[h*C + d];
            sAk[d] = ak + kb[h*C + d];
        }
        __syncthreads();
        if (t < C) {
            int o = t;
            float sbv = sb[o];
#pragma unroll
            for (int v = 0; v < 9; v++) {
                float acc = 0.f;
#pragma unroll 8
                for (int c = 0; c < C; c++)
                    acc += sAk[c] * g_S2[(v*C + c)*C + o];
                g_Cs[((n*H + h)*C + o)*9 + v] = (acc + sbv) * SCALE;
            }
        }
    } else {
        // ---- Gx / Gy ----
        int b2 = b - 64;
        int v   = b2 % 3;
        int o   = (b2/3) % C;
        int h   = (b2/(3*C)) % H;
        int tab = b2 / (3*C*H);
        int p = t;
        __shared__ float cs[C*3];
        for (int q = p; q < C*3; q += 96) {
            int c = q/3, k = q%3;
            float acc = 0.f;
#pragma unroll
            for (int qq = 0; qq < 3; qq++) {
                if (v == 0 && qq == 0) continue;
                if (v == 2 && qq == 2) continue;
                acc += (tab == 0) ? sw[(o*C + c)*9 + qq*3 + k]
                                  : sw[(o*C + c)*9 + k*3 + qq];
            }
            cs[q] = acc;
        }
        __syncthreads();
        const float* src = (tab == 0) ? (g_Bxk + h*C*I) : (g_Byk + h*C*I);
        float val = 0.f;
#pragma unroll
        for (int k = 0; k < 3; k++) {
            int q = p + k - 1;
            if (q < 0 || q >= I) continue;
            for (int c = 0; c < C; c++)
                val += cs[c*3 + k] * src[c*I + q];
        }
        float* dst = (tab == 0) ? g_Gx : g_Gy;
        dst[((h*C + o)*3 + v)*I + p] = val * SCALE;
    }
}

// ============================================================================
// Launch 3: ALL 321 MB of stores in one kernel — softmax w, T, and P.
// grid (24, 64, 8), 96 threads
// ============================================================================
__global__ void __launch_bounds__(96) k_WTP(const float* __restrict__ px,
                                            const float* __restrict__ py,
                                            float* __restrict__ out) {
    __shared__ float sGx[H][I];    // vy = 1 slice
    __shared__ float sVx[H][I];
    __shared__ float sPx[I];       // px row (c < C2 only)
    __shared__ float sBase[32], sE0[32], sE2[32], sVb[32], sPb[32];

    int t = threadIdx.x;
    int bx = blockIdx.x, c = blockIdx.y, n = blockIdx.z;

    if (t < 32) {
        int h = t >> 2, il = t & 3;
        int ii = bx*4 + il;
        int vy = (ii == 0) ? 0 : (ii == (I-1) ? 2 : 1);
        const float* cs = g_Cs + ((n*H + h)*C + c)*9 + vy*3;
        const float* gy = g_Gy + (h*C + c)*3*I;
        sBase[t] = cs[1] + gy[I + ii];
        sE0[t]   = cs[0] + gy[ii];
        sE2[t]   = cs[2] + gy[2*I + ii];
        sVb[t]   = g_Av[(n*H + h)*C + c] + g_Vy[(h*C + c)*I + ii];
        sPb[t]   = (c < C2) ? g_M[(n*H + h)*C2 + c]
                            : g_M[(n*H + h)*C2 + (c - C2)] + __ldg(py + (c - C2)*I + ii);
    }
#pragma unroll
    for (int q = t; q < 2*I; q += 96) {     // 192 float4 slots = 8h x 24
        int h = q / 24, j4 = q % 24;
        *(float4*)&sGx[h][j4*4] = *(const float4*)(g_Gx + ((h*C + c)*3 + 1)*I + j4*4);
        *(float4*)&sVx[h][j4*4] = *(const float4*)(g_Vx + (h*C + c)*I + j4*4);
    }
    if (c < C2 && t < 24)
        *(float4*)&sPx[t*4] = *(const float4*)(px + c*I + t*4);
    __syncthreads();

    int j4 = t % 24, il = t / 24;
    int ii = bx*4 + il, jj0 = j4*4;
    int vy = (ii == 0) ? 0 : (ii == (I-1) ? 2 : 1);
    int hb = il;

    float s[H][4];
    float mx0 = -1e30f, mx1 = -1e30f, mx2 = -1e30f, mx3 = -1e30f;
#pragma unroll
    for (int h = 0; h < H; h++) {
        float4 gx = (vy == 1) ? *(const float4*)&sGx[h][jj0]
                              : *(const float4*)(g_Gx + ((h*C + c)*3 + vy)*I + jj0);
        float base = sBase[h*4 + hb];
        float s0 = base + gx.x, s1 = base + gx.y, s2 = base + gx.z, s3 = base + gx.w;
        if (jj0 == 0)     s0 = sE0[h*4 + hb] + gx.x;
        if (jj0 == I - 4) s3 = sE2[h*4 + hb] + gx.w;
        s[h][0] = s0; s[h][1] = s1; s[h][2] = s2; s[h][3] = s3;
        mx0 = fmaxf(mx0, s0); mx1 = fmaxf(mx1, s1);
        mx2 = fmaxf(mx2, s2); mx3 = fmaxf(mx3, s3);
    }
    float sum0 = 0.f, sum1 = 0.f, sum2 = 0.f, sum3 = 0.f;
#pragma unroll
    for (int h = 0; h < H; h++) {
        s[h][0] = __expf(s[h][0] - mx0); sum0 += s[h][0];
        s[h][1] = __expf(s[h][1] - mx1); sum1 += s[h][1];
        s[h][2] = __expf(s[h][2] - mx2); sum2 += s[h][2];
        s[h][3] = __expf(s[h][3] - mx3); sum3 += s[h][3];
    }
    float i0 = __fdividef(1.f, sum0), i1 = __fdividef(1.f, sum1);
    float i2 = __fdividef(1.f, sum2), i3 = __fdividef(1.f, sum3);

    float4 px4 = make_float4(0.f, 0.f, 0.f, 0.f);
    if (c < C2) px4 = *(const float4*)&sPx[jj0];

    float4 acc = make_float4(0.f, 0.f, 0.f, 0.f);
    int pixbase = ii*I + jj0;
#pragma unroll
    for (int h = 0; h < H; h++) {
        float w0 = s[h][0]*i0, w1 = s[h][1]*i1, w2 = s[h][2]*i2, w3 = s[h][3]*i3;
        size_t idx = (size_t)((n*H + h)*C + c)*I*I + pixbase;
        __stcs((float4*)(out + OFF_W + idx), make_float4(w0, w1, w2, w3));

        float vb = sVb[h*4 + hb];
        const float4 vx4 = *(const float4*)&sVx[h][jj0];
        acc.x += w0*(vb + vx4.x);
        acc.y += w1*(vb + vx4.y);
        acc.z += w2*(vb + vx4.z);
        acc.w += w3*(vb + vx4.w);

        float pb = sPb[h*4 + hb];
        float4 pv = (c < C2) ? make_float4(pb + px4.x, pb + px4.y, pb + px4.z, pb + px4.w)
                             : make_float4(pb, pb, pb, pb);
        __stcs((float4*)(out + OFF_P + idx), pv);
    }
    __stcs((float4*)(out + OFF_T + (size_t)(n*C + c)*I*I + pixbase), acc);
}

// ---------------- launch ----------------
extern "C" void kernel_launch(void* const* d_in, const int* in_sizes, int n_in,
                              void* d_out, int out_size) {
    (void)in_sizes; (void)n_in; (void)out_size;
    const float* X     = (const float*)d_in[0];
    const float* lin_w = (const float*)d_in[1];
    const float* lin_b = (const float*)d_in[2];
    const float* gamma = (const float*)d_in[3];
    const float* beta  = (const float*)d_in[4];
    const float* px    = (const float*)d_in[5];
    const float* py    = (const float*)d_in[6];
    const float* kw    = (const float*)d_in[7];
    const float* kb    = (const float*)d_in[8];
    const float* vw    = (const float*)d_in[9];
    const float* vb    = (const float*)d_in[10];
    const float* sw    = (const float*)d_in[11];
    const float* sb    = (const float*)d_in[12];
    float* out = (float*)d_out;

    k_setup1<<<832, 256>>>(X, lin_w, lin_b, gamma, beta, px, py, kw, vw, sw, out);
    k_setup2<<<3136, 96>>>(kw, kb, vw, vb, sw, sb);
    k_WTP<<<dim3(I/4, C, NN), 96>>>(px, py, out);
}